// round 1
// baseline (speedup 1.0000x reference)
#include <cuda_runtime.h>
#include <cstddef>

// Problem constants (fixed shapes from reference)
#define T_    4096
#define DIN   512
#define RR    4096
#define DOUT  512
#define NINT  (RR + DIN)   // 4608
#define LEAK_ 0.9f

// ---------------------------------------------------------------------------
// Scratch (static __device__ arrays; runtime allocation is forbidden)
// ---------------------------------------------------------------------------
__device__ float g_u[(size_t)T_ * RR];        // 64 MB: u = x @ Win^T + b
__device__ float g_states[(size_t)T_ * RR];   // 64 MB: all reservoir states

// Grid-barrier state for the persistent recurrence kernel
__device__ unsigned g_count = 0;
__device__ volatile unsigned g_gen = 0;

// ---------------------------------------------------------------------------
// Software grid barrier (persistent kernel, all CTAs co-resident).
// Release: __threadfence before arrive pushes this CTA's state writes to L2.
// Acquire: __threadfence after observing the generation bump emits
// CCTL.IVALL (fence scope >= cluster) so stale L1 lines of s are dropped.
// ---------------------------------------------------------------------------
__device__ __forceinline__ void grid_barrier(int nctas)
{
    __syncthreads();
    if (threadIdx.x == 0) {
        __threadfence();                      // release
        unsigned gen = g_gen;
        if (atomicAdd(&g_count, 1u) == (unsigned)(nctas - 1)) {
            g_count = 0;
            __threadfence();
            g_gen = gen + 1u;                 // release the pack
        } else {
            while (g_gen == gen) { }          // volatile spin
        }
        __threadfence();                      // acquire (invalidates L1D)
    }
    __syncthreads();
}

// ---------------------------------------------------------------------------
// GEMM 1: g_u[t][r] = sum_d x[t,d] * Win_w[r,d] + Win_b[r]
// 128x128 C-tile, 256 threads, 8x8 per-thread microtile, K-tile 8.
// Both A and B are K-contiguous (dot of rows).
// ---------------------------------------------------------------------------
__global__ __launch_bounds__(256) void gemm_u_kernel(
    const float* __restrict__ A,     // x: (T_, DIN)
    const float* __restrict__ B,     // Win_w: (RR, DIN)
    const float* __restrict__ bias)  // Win_b: (RR)
{
    const int K = DIN;
    __shared__ float As[8][128];
    __shared__ float Bs[8][128];

    const int bm = blockIdx.y * 128;
    const int bn = blockIdx.x * 128;
    const int tid = threadIdx.x;
    const int tm = (tid >> 4) * 8;
    const int tn = (tid & 15) * 8;
    const int lr = tid >> 1;
    const int lc = (tid & 1) * 4;

    float acc[8][8];
    #pragma unroll
    for (int i = 0; i < 8; i++)
        #pragma unroll
        for (int j = 0; j < 8; j++) acc[i][j] = 0.f;

    for (int kb = 0; kb < K; kb += 8) {
        float4 a = *reinterpret_cast<const float4*>(&A[(size_t)(bm + lr) * K + kb + lc]);
        float4 b = *reinterpret_cast<const float4*>(&B[(size_t)(bn + lr) * K + kb + lc]);
        __syncthreads();
        As[lc + 0][lr] = a.x; As[lc + 1][lr] = a.y; As[lc + 2][lr] = a.z; As[lc + 3][lr] = a.w;
        Bs[lc + 0][lr] = b.x; Bs[lc + 1][lr] = b.y; Bs[lc + 2][lr] = b.z; Bs[lc + 3][lr] = b.w;
        __syncthreads();
        #pragma unroll
        for (int k = 0; k < 8; k++) {
            float4 a0 = *reinterpret_cast<const float4*>(&As[k][tm]);
            float4 a1 = *reinterpret_cast<const float4*>(&As[k][tm + 4]);
            float4 b0 = *reinterpret_cast<const float4*>(&Bs[k][tn]);
            float4 b1 = *reinterpret_cast<const float4*>(&Bs[k][tn + 4]);
            float ar[8] = {a0.x, a0.y, a0.z, a0.w, a1.x, a1.y, a1.z, a1.w};
            float br[8] = {b0.x, b0.y, b0.z, b0.w, b1.x, b1.y, b1.z, b1.w};
            #pragma unroll
            for (int i = 0; i < 8; i++)
                #pragma unroll
                for (int j = 0; j < 8; j++)
                    acc[i][j] = fmaf(ar[i], br[j], acc[i][j]);
        }
    }

    #pragma unroll
    for (int i = 0; i < 8; i++)
        #pragma unroll
        for (int j = 0; j < 8; j++)
            g_u[(size_t)(bm + tm + i) * RR + (bn + tn + j)] = acc[i][j] + bias[bn + tn + j];
}

// ---------------------------------------------------------------------------
// Persistent recurrence kernel.
//  step 0: states[0] = tanh(u[0])
//  step t: xi = tanh(u[t] + Wres @ s_{t-1}); s_t = 0.1*s_{t-1} + 0.9*xi
// One warp per reservoir row; rows split evenly across nctas CTAs so every
// SM pulls an equal share (~27-28 rows = ~448 KB/step) from L2.
// ---------------------------------------------------------------------------
__global__ __launch_bounds__(1024, 1) void recur_kernel(
    const float* __restrict__ Wres, int nctas)
{
    const int cta   = blockIdx.x;
    const int r0    = (cta * RR) / nctas;
    const int r1    = ((cta + 1) * RR) / nctas;
    const int nrows = r1 - r0;
    const int warp  = threadIdx.x >> 5;
    const int lane  = threadIdx.x & 31;

    // step 0
    if (threadIdx.x < nrows) {
        int r = r0 + threadIdx.x;
        g_states[r] = tanhf(g_u[r]);
    }
    grid_barrier(nctas);

    const float4* wrow4 = nullptr;
    int r = 0;
    if (warp < nrows) {
        r = r0 + warp;
        wrow4 = reinterpret_cast<const float4*>(Wres + (size_t)r * RR);
    }

    for (int t = 1; t < T_; ++t) {
        const float* sprev = g_states + (size_t)(t - 1) * RR;
        float*       scur  = g_states + (size_t)t * RR;
        if (warp < nrows) {
            const float4* sp4 = reinterpret_cast<const float4*>(sprev);
            float acc = 0.f;
            #pragma unroll 4
            for (int i = lane; i < RR / 4; i += 32) {
                float4 w = wrow4[i];
                float4 s = sp4[i];
                acc = fmaf(w.x, s.x, acc);
                acc = fmaf(w.y, s.y, acc);
                acc = fmaf(w.z, s.z, acc);
                acc = fmaf(w.w, s.w, acc);
            }
            #pragma unroll
            for (int o = 16; o; o >>= 1)
                acc += __shfl_xor_sync(0xffffffffu, acc, o);
            if (lane == 0) {
                float xi = tanhf(g_u[(size_t)t * RR + r] + acc);
                scur[r] = (1.0f - LEAK_) * sprev[r] + LEAK_ * xi;
            }
        }
        grid_barrier(nctas);
    }
}

// ---------------------------------------------------------------------------
// GEMM 2: yout[t][o] = sum_k xall[t,k] * Wout_w[o,k] + Wout_b[o]
// xall = concat(x, states) handled by a piecewise A-loader (K split at 512,
// K-tile of 8 never straddles the boundary).
// ---------------------------------------------------------------------------
__global__ __launch_bounds__(256) void gemm_out_kernel(
    const float* __restrict__ x,      // (T_, DIN)
    const float* __restrict__ Wout,   // (DOUT, NINT)
    const float* __restrict__ bias,   // (DOUT)
    float* __restrict__ C)            // yout: (T_, DOUT)
{
    const int K = NINT;
    __shared__ float As[8][128];
    __shared__ float Bs[8][128];

    const int bm = blockIdx.y * 128;
    const int bn = blockIdx.x * 128;
    const int tid = threadIdx.x;
    const int tm = (tid >> 4) * 8;
    const int tn = (tid & 15) * 8;
    const int lr = tid >> 1;
    const int lc = (tid & 1) * 4;

    float acc[8][8];
    #pragma unroll
    for (int i = 0; i < 8; i++)
        #pragma unroll
        for (int j = 0; j < 8; j++) acc[i][j] = 0.f;

    for (int kb = 0; kb < K; kb += 8) {
        const int row = bm + lr;
        const int kk  = kb + lc;
        float4 a;
        if (kk < DIN)
            a = *reinterpret_cast<const float4*>(&x[(size_t)row * DIN + kk]);
        else
            a = *reinterpret_cast<const float4*>(&g_states[(size_t)row * RR + (kk - DIN)]);
        float4 b = *reinterpret_cast<const float4*>(&Wout[(size_t)(bn + lr) * K + kk]);
        __syncthreads();
        As[lc + 0][lr] = a.x; As[lc + 1][lr] = a.y; As[lc + 2][lr] = a.z; As[lc + 3][lr] = a.w;
        Bs[lc + 0][lr] = b.x; Bs[lc + 1][lr] = b.y; Bs[lc + 2][lr] = b.z; Bs[lc + 3][lr] = b.w;
        __syncthreads();
        #pragma unroll
        for (int k = 0; k < 8; k++) {
            float4 a0 = *reinterpret_cast<const float4*>(&As[k][tm]);
            float4 a1 = *reinterpret_cast<const float4*>(&As[k][tm + 4]);
            float4 b0 = *reinterpret_cast<const float4*>(&Bs[k][tn]);
            float4 b1 = *reinterpret_cast<const float4*>(&Bs[k][tn + 4]);
            float ar[8] = {a0.x, a0.y, a0.z, a0.w, a1.x, a1.y, a1.z, a1.w};
            float br[8] = {b0.x, b0.y, b0.z, b0.w, b1.x, b1.y, b1.z, b1.w};
            #pragma unroll
            for (int i = 0; i < 8; i++)
                #pragma unroll
                for (int j = 0; j < 8; j++)
                    acc[i][j] = fmaf(ar[i], br[j], acc[i][j]);
        }
    }

    #pragma unroll
    for (int i = 0; i < 8; i++)
        #pragma unroll
        for (int j = 0; j < 8; j++)
            C[(size_t)(bm + tm + i) * DOUT + (bn + tn + j)] = acc[i][j] + bias[bn + tn + j];
}

// ---------------------------------------------------------------------------
// Launch: gemm_u -> persistent recurrence -> gemm_out (default stream, ordered)
// ---------------------------------------------------------------------------
extern "C" void kernel_launch(void* const* d_in, const int* in_sizes, int n_in,
                              void* d_out, int out_size)
{
    const float* x      = (const float*)d_in[0];
    const float* Win_w  = (const float*)d_in[1];
    const float* Win_b  = (const float*)d_in[2];
    const float* Wres_w = (const float*)d_in[3];
    const float* Wout_w = (const float*)d_in[4];
    const float* Wout_b = (const float*)d_in[5];
    float* yout = (float*)d_out;

    int dev = 0;
    cudaGetDevice(&dev);
    int sms = 148;
    cudaDeviceGetAttribute(&sms, cudaDevAttrMultiProcessorCount, dev);
    if (sms < 1) sms = 1;

    dim3 g1(RR / 128, T_ / 128);
    gemm_u_kernel<<<g1, 256>>>(x, Win_w, Win_b);

    recur_kernel<<<sms, 1024>>>(Wres_w, sms);

    dim3 g2(DOUT / 128, T_ / 128);
    gemm_out_kernel<<<g2, 256>>>(x, Wout_w, Wout_b, yout);

    (void)in_sizes; (void)n_in; (void)out_size;
}

// round 4
// speedup vs baseline: 1.0178x; 1.0178x over previous
#include <cuda_runtime.h>
#include <cstddef>

// Problem constants (fixed shapes from reference)
#define T_    4096
#define DIN   512
#define RR    4096
#define DOUT  512
#define NINT  (RR + DIN)   // 4608
#define LEAK_ 0.9f

#define NCTAS      148          // SM count (verified at launch)
#define ROWS_MAX   28           // ceil(4096/148)
#define C_S        1792         // columns of each row resident in SMEM
#define C_S4       (C_S / 4)    // 448 float4
#define SMEM_W_FLOATS ((size_t)ROWS_MAX * C_S)
#define SMEM_BYTES ((SMEM_W_FLOATS + RR) * sizeof(float))  // 200704 + 16384 = 217088

// ---------------------------------------------------------------------------
// Scratch (static __device__ arrays; runtime allocation is forbidden)
// ---------------------------------------------------------------------------
__device__ float g_u[(size_t)T_ * RR];        // 64 MB: u = x @ Win^T + b
__device__ float g_states[(size_t)T_ * RR];   // 64 MB: all reservoir states

// Grid-barrier state for the persistent recurrence kernel
__device__ unsigned g_count = 0;
__device__ volatile unsigned g_gen = 0;

__device__ __forceinline__ float ldcg(const float* p) { return __ldcg(p); }
__device__ __forceinline__ float4 ldcg4(const float4* p) {
    float4 v;
    asm volatile("ld.global.cg.v4.f32 {%0,%1,%2,%3}, [%4];"
                 : "=f"(v.x), "=f"(v.y), "=f"(v.z), "=f"(v.w) : "l"(p));
    return v;
}

// ---------------------------------------------------------------------------
// Software grid barrier (persistent kernel, all CTAs co-resident).
// ---------------------------------------------------------------------------
__device__ __forceinline__ void grid_barrier(int nctas)
{
    __syncthreads();
    if (threadIdx.x == 0) {
        __threadfence();                      // release
        unsigned gen = g_gen;
        if (atomicAdd(&g_count, 1u) == (unsigned)(nctas - 1)) {
            g_count = 0;
            __threadfence();
            g_gen = gen + 1u;                 // release the pack
        } else {
            while (g_gen == gen) { }          // volatile spin
        }
        __threadfence();                      // acquire
    }
    __syncthreads();
}

// ---------------------------------------------------------------------------
// GEMM 1: g_u[t][r] = sum_d x[t,d] * Win_w[r,d] + Win_b[r]
// ---------------------------------------------------------------------------
__global__ __launch_bounds__(256) void gemm_u_kernel(
    const float* __restrict__ A,     // x: (T_, DIN)
    const float* __restrict__ B,     // Win_w: (RR, DIN)
    const float* __restrict__ bias)  // Win_b: (RR)
{
    const int K = DIN;
    __shared__ float As[8][128];
    __shared__ float Bs[8][128];

    const int bm = blockIdx.y * 128;
    const int bn = blockIdx.x * 128;
    const int tid = threadIdx.x;
    const int tm = (tid >> 4) * 8;
    const int tn = (tid & 15) * 8;
    const int lr = tid >> 1;
    const int lc = (tid & 1) * 4;

    float acc[8][8];
    #pragma unroll
    for (int i = 0; i < 8; i++)
        #pragma unroll
        for (int j = 0; j < 8; j++) acc[i][j] = 0.f;

    for (int kb = 0; kb < K; kb += 8) {
        float4 a = *reinterpret_cast<const float4*>(&A[(size_t)(bm + lr) * K + kb + lc]);
        float4 b = *reinterpret_cast<const float4*>(&B[(size_t)(bn + lr) * K + kb + lc]);
        __syncthreads();
        As[lc + 0][lr] = a.x; As[lc + 1][lr] = a.y; As[lc + 2][lr] = a.z; As[lc + 3][lr] = a.w;
        Bs[lc + 0][lr] = b.x; Bs[lc + 1][lr] = b.y; Bs[lc + 2][lr] = b.z; Bs[lc + 3][lr] = b.w;
        __syncthreads();
        #pragma unroll
        for (int k = 0; k < 8; k++) {
            float4 a0 = *reinterpret_cast<const float4*>(&As[k][tm]);
            float4 a1 = *reinterpret_cast<const float4*>(&As[k][tm + 4]);
            float4 b0 = *reinterpret_cast<const float4*>(&Bs[k][tn]);
            float4 b1 = *reinterpret_cast<const float4*>(&Bs[k][tn + 4]);
            float ar[8] = {a0.x, a0.y, a0.z, a0.w, a1.x, a1.y, a1.z, a1.w};
            float br[8] = {b0.x, b0.y, b0.z, b0.w, b1.x, b1.y, b1.z, b1.w};
            #pragma unroll
            for (int i = 0; i < 8; i++)
                #pragma unroll
                for (int j = 0; j < 8; j++)
                    acc[i][j] = fmaf(ar[i], br[j], acc[i][j]);
        }
    }

    #pragma unroll
    for (int i = 0; i < 8; i++)
        #pragma unroll
        for (int j = 0; j < 8; j++)
            g_u[(size_t)(bm + tm + i) * RR + (bn + tn + j)] = acc[i][j] + bias[bn + tn + j];
}

// ---------------------------------------------------------------------------
// Persistent recurrence kernel, SMEM-split variant.
// Each CTA owns rows [r0, r1). The first C_S columns of those rows live in
// SMEM (loaded once); the remaining columns stream from L2 every step.
// s_{t-1} is staged into SMEM per step; each warp computes 2 rows (s reuse).
// ---------------------------------------------------------------------------
extern __shared__ float s_dyn[];   // [SMEM_W_FLOATS weights][RR staged s]

__global__ __launch_bounds__(1024, 1) void recur_kernel(
    const float* __restrict__ Wres, int nctas)
{
    float* wsh  = s_dyn;                     // ROWS_MAX * C_S
    float* s_sh = s_dyn + SMEM_W_FLOATS;     // RR floats
    float4* s_sh4 = reinterpret_cast<float4*>(s_sh);

    const int cta   = blockIdx.x;
    const int r0    = (cta * RR) / nctas;
    const int r1    = ((cta + 1) * RR) / nctas;
    const int nrows = r1 - r0;
    const int warp  = threadIdx.x >> 5;
    const int lane  = threadIdx.x & 31;
    const int tid   = threadIdx.x;

    // ---- Prologue: load SMEM-resident weight block (rows r0.., cols [0,C_S))
    {
        const int tot4 = nrows * C_S4;
        for (int idx = tid; idx < tot4; idx += 1024) {
            int lrow = idx / C_S4;
            int c4   = idx - lrow * C_S4;
            reinterpret_cast<float4*>(wsh)[(size_t)lrow * C_S4 + c4] =
                ldcg4(reinterpret_cast<const float4*>(Wres + (size_t)(r0 + lrow) * RR) + c4);
        }
    }

    // ---- step 0: states[0] = tanh(u[0])
    if (tid < nrows) {
        int r = r0 + tid;
        g_states[r] = tanhf(ldcg(&g_u[r]));
    }
    grid_barrier(nctas);

    const int npairs = (nrows + 1) >> 1;       // warps doing work (<= 14)
    const int rowA = r0 + 2 * warp;            // global row indices for this warp
    const int rowB = rowA + 1;
    const bool active = (warp < npairs);
    const bool haveB  = active && (rowB < r1);

    const float4* wgA = reinterpret_cast<const float4*>(Wres + (size_t)rowA * RR);
    const float4* wgB = reinterpret_cast<const float4*>(Wres + (size_t)rowB * RR);
    const float4* wsA = reinterpret_cast<const float4*>(wsh + (size_t)(2 * warp) * C_S);
    const float4* wsB = reinterpret_cast<const float4*>(wsh + (size_t)(2 * warp + 1) * C_S);

    for (int t = 1; t < T_; ++t) {
        // Stage s_{t-1} into SMEM (bypass L1; L2-fresh after barrier)
        {
            const float4* sp4 = reinterpret_cast<const float4*>(
                g_states + (size_t)(t - 1) * RR);
            s_sh4[tid] = ldcg4(sp4 + tid);     // 1024 threads x float4 = 4096 floats
        }
        __syncthreads();

        if (active) {
            float accA = 0.f, accB = 0.f;

            // SMEM-resident columns [0, C_S)
            #pragma unroll 4
            for (int i = lane; i < C_S4; i += 32) {
                float4 s = s_sh4[i];
                float4 a = wsA[i];
                accA = fmaf(a.x, s.x, accA); accA = fmaf(a.y, s.y, accA);
                accA = fmaf(a.z, s.z, accA); accA = fmaf(a.w, s.w, accA);
                if (haveB) {
                    float4 b = wsB[i];
                    accB = fmaf(b.x, s.x, accB); accB = fmaf(b.y, s.y, accB);
                    accB = fmaf(b.z, s.z, accB); accB = fmaf(b.w, s.w, accB);
                }
            }
            // L2-streamed columns [C_S, RR)
            #pragma unroll 4
            for (int i = C_S4 + lane; i < RR / 4; i += 32) {
                float4 s = s_sh4[i];
                float4 a = ldcg4(wgA + i);
                accA = fmaf(a.x, s.x, accA); accA = fmaf(a.y, s.y, accA);
                accA = fmaf(a.z, s.z, accA); accA = fmaf(a.w, s.w, accA);
                if (haveB) {
                    float4 b = ldcg4(wgB + i);
                    accB = fmaf(b.x, s.x, accB); accB = fmaf(b.y, s.y, accB);
                    accB = fmaf(b.z, s.z, accB); accB = fmaf(b.w, s.w, accB);
                }
            }

            #pragma unroll
            for (int o = 16; o; o >>= 1) {
                accA += __shfl_xor_sync(0xffffffffu, accA, o);
                accB += __shfl_xor_sync(0xffffffffu, accB, o);
            }
            if (lane == 0) {
                const float* u_t = g_u + (size_t)t * RR;
                float* scur = g_states + (size_t)t * RR;
                float xiA = tanhf(ldcg(&u_t[rowA]) + accA);
                scur[rowA] = (1.0f - LEAK_) * s_sh[rowA] + LEAK_ * xiA;
                if (haveB) {
                    float xiB = tanhf(ldcg(&u_t[rowB]) + accB);
                    scur[rowB] = (1.0f - LEAK_) * s_sh[rowB] + LEAK_ * xiB;
                }
            }
        }
        grid_barrier(nctas);
    }
}

// ---------------------------------------------------------------------------
// Fallback recurrence (identical to the R1 kernel that passed): no dynamic
// SMEM, one warp per row, Wres streamed from L2 every step.
// ---------------------------------------------------------------------------
__global__ __launch_bounds__(1024, 1) void recur_fallback(
    const float* __restrict__ Wres, int nctas)
{
    const int cta   = blockIdx.x;
    const int r0    = (cta * RR) / nctas;
    const int r1    = ((cta + 1) * RR) / nctas;
    const int nrows = r1 - r0;
    const int warp  = threadIdx.x >> 5;
    const int lane  = threadIdx.x & 31;

    if (threadIdx.x < nrows) {
        int r = r0 + threadIdx.x;
        g_states[r] = tanhf(g_u[r]);
    }
    grid_barrier(nctas);

    const float4* wrow4 = nullptr;
    int r = 0;
    if (warp < nrows) {
        r = r0 + warp;
        wrow4 = reinterpret_cast<const float4*>(Wres + (size_t)r * RR);
    }

    for (int t = 1; t < T_; ++t) {
        const float* sprev = g_states + (size_t)(t - 1) * RR;
        float*       scur  = g_states + (size_t)t * RR;
        if (warp < nrows) {
            const float4* sp4 = reinterpret_cast<const float4*>(sprev);
            float acc = 0.f;
            #pragma unroll 4
            for (int i = lane; i < RR / 4; i += 32) {
                float4 w = wrow4[i];
                float4 s = sp4[i];
                acc = fmaf(w.x, s.x, acc);
                acc = fmaf(w.y, s.y, acc);
                acc = fmaf(w.z, s.z, acc);
                acc = fmaf(w.w, s.w, acc);
            }
            #pragma unroll
            for (int o = 16; o; o >>= 1)
                acc += __shfl_xor_sync(0xffffffffu, acc, o);
            if (lane == 0) {
                float xi = tanhf(g_u[(size_t)t * RR + r] + acc);
                scur[r] = (1.0f - LEAK_) * sprev[r] + LEAK_ * xi;
            }
        }
        grid_barrier(nctas);
    }
}

// ---------------------------------------------------------------------------
// GEMM 2: yout[t][o] = sum_k concat(x, states)[t,k] * Wout_w[o,k] + Wout_b[o]
// ---------------------------------------------------------------------------
__global__ __launch_bounds__(256) void gemm_out_kernel(
    const float* __restrict__ x,      // (T_, DIN)
    const float* __restrict__ Wout,   // (DOUT, NINT)
    const float* __restrict__ bias,   // (DOUT)
    float* __restrict__ C)            // yout: (T_, DOUT)
{
    const int K = NINT;
    __shared__ float As[8][128];
    __shared__ float Bs[8][128];

    const int bm = blockIdx.y * 128;
    const int bn = blockIdx.x * 128;
    const int tid = threadIdx.x;
    const int tm = (tid >> 4) * 8;
    const int tn = (tid & 15) * 8;
    const int lr = tid >> 1;
    const int lc = (tid & 1) * 4;

    float acc[8][8];
    #pragma unroll
    for (int i = 0; i < 8; i++)
        #pragma unroll
        for (int j = 0; j < 8; j++) acc[i][j] = 0.f;

    for (int kb = 0; kb < K; kb += 8) {
        const int row = bm + lr;
        const int kk  = kb + lc;
        float4 a;
        if (kk < DIN)
            a = *reinterpret_cast<const float4*>(&x[(size_t)row * DIN + kk]);
        else
            a = *reinterpret_cast<const float4*>(&g_states[(size_t)row * RR + (kk - DIN)]);
        float4 b = *reinterpret_cast<const float4*>(&Wout[(size_t)(bn + lr) * K + kk]);
        __syncthreads();
        As[lc + 0][lr] = a.x; As[lc + 1][lr] = a.y; As[lc + 2][lr] = a.z; As[lc + 3][lr] = a.w;
        Bs[lc + 0][lr] = b.x; Bs[lc + 1][lr] = b.y; Bs[lc + 2][lr] = b.z; Bs[lc + 3][lr] = b.w;
        __syncthreads();
        #pragma unroll
        for (int k = 0; k < 8; k++) {
            float4 a0 = *reinterpret_cast<const float4*>(&As[k][tm]);
            float4 a1 = *reinterpret_cast<const float4*>(&As[k][tm + 4]);
            float4 b0 = *reinterpret_cast<const float4*>(&Bs[k][tn]);
            float4 b1 = *reinterpret_cast<const float4*>(&Bs[k][tn + 4]);
            float ar[8] = {a0.x, a0.y, a0.z, a0.w, a1.x, a1.y, a1.z, a1.w};
            float br[8] = {b0.x, b0.y, b0.z, b0.w, b1.x, b1.y, b1.z, b1.w};
            #pragma unroll
            for (int i = 0; i < 8; i++)
                #pragma unroll
                for (int j = 0; j < 8; j++)
                    acc[i][j] = fmaf(ar[i], br[j], acc[i][j]);
        }
    }

    #pragma unroll
    for (int i = 0; i < 8; i++)
        #pragma unroll
        for (int j = 0; j < 8; j++)
            C[(size_t)(bm + tm + i) * DOUT + (bn + tn + j)] = acc[i][j] + bias[bn + tn + j];
}

// ---------------------------------------------------------------------------
// Launch: gemm_u -> persistent recurrence -> gemm_out (default stream, ordered)
// Residency gate: only launch the big-SMEM variant if the occupancy API
// confirms >= 1 resident CTA/SM with that config; otherwise use the proven
// no-SMEM fallback. Deterministic host logic; no static state.
// ---------------------------------------------------------------------------
extern "C" void kernel_launch(void* const* d_in, const int* in_sizes, int n_in,
                              void* d_out, int out_size)
{
    const float* x      = (const float*)d_in[0];
    const float* Win_w  = (const float*)d_in[1];
    const float* Win_b  = (const float*)d_in[2];
    const float* Wres_w = (const float*)d_in[3];
    const float* Wout_w = (const float*)d_in[4];
    const float* Wout_b = (const float*)d_in[5];
    float* yout = (float*)d_out;

    int dev = 0;
    cudaGetDevice(&dev);
    int sms = NCTAS;
    cudaDeviceGetAttribute(&sms, cudaDevAttrMultiProcessorCount, dev);
    if (sms < 1 || sms > NCTAS) sms = NCTAS;

    cudaError_t attr_err = cudaFuncSetAttribute(
        recur_kernel, cudaFuncAttributeMaxDynamicSharedMemorySize, (int)SMEM_BYTES);

    int nblk = 0;
    cudaError_t occ_err = cudaOccupancyMaxActiveBlocksPerMultiprocessor(
        &nblk, recur_kernel, 1024, SMEM_BYTES);
    const bool use_smem = (attr_err == cudaSuccess) &&
                          (occ_err == cudaSuccess) && (nblk >= 1);

    dim3 g1(RR / 128, T_ / 128);
    gemm_u_kernel<<<g1, 256>>>(x, Win_w, Win_b);

    if (use_smem)
        recur_kernel<<<sms, 1024, SMEM_BYTES>>>(Wres_w, sms);
    else
        recur_fallback<<<sms, 1024>>>(Wres_w, sms);

    dim3 g2(DOUT / 128, T_ / 128);
    gemm_out_kernel<<<g2, 256>>>(x, Wout_w, Wout_b, yout);

    (void)in_sizes; (void)n_in; (void)out_size;
}

// round 5
// speedup vs baseline: 1.1117x; 1.0923x over previous
#include <cuda_runtime.h>
#include <cuda_fp16.h>
#include <cstddef>
#include <cstdint>

// Problem constants (fixed shapes from reference)
#define T_    4096
#define DIN   512
#define RR    4096
#define DOUT  512
#define NINT  (RR + DIN)   // 4608
#define LEAK_ 0.9f

#define NCTAS      148          // SM count (verified at launch)
#define ROWS_MAX   28           // ceil(4096/148)
#define C_SH       3584         // half-cols of each row resident in SMEM
#define C_SH8      (C_SH / 8)   // 448 chunks of 8 halves
#define REM8       ((RR - C_SH) / 8)  // 64 streamed chunks
#define SMEM_BYTES ((size_t)ROWS_MAX * C_SH * 2 + RR * 4)  // 200704+16384=217088

// ---------------------------------------------------------------------------
// Scratch (static __device__ arrays; runtime allocation is forbidden)
// ---------------------------------------------------------------------------
__device__ float  g_u[(size_t)T_ * RR];        // 64 MB
__device__ float  g_states[(size_t)T_ * RR];   // 64 MB
__device__ __half g_wres_h[(size_t)RR * RR];   // 32 MB: fp16 copy of Wres

// Grid-barrier state
__device__ unsigned g_count = 0;
__device__ volatile unsigned g_gen = 0;

__device__ __forceinline__ float ldcg(const float* p) { return __ldcg(p); }
__device__ __forceinline__ float4 ldcg4f(const float4* p) {
    float4 v;
    asm volatile("ld.global.cg.v4.f32 {%0,%1,%2,%3}, [%4];"
                 : "=f"(v.x), "=f"(v.y), "=f"(v.z), "=f"(v.w) : "l"(p));
    return v;
}
__device__ __forceinline__ uint4 ldcg4u(const uint4* p) {
    uint4 v;
    asm volatile("ld.global.cg.v4.u32 {%0,%1,%2,%3}, [%4];"
                 : "=r"(v.x), "=r"(v.y), "=r"(v.z), "=r"(v.w) : "l"(p));
    return v;
}

// 8 halves (packed in uint4) * 8 floats -> acc
__device__ __forceinline__ void fma8(uint4 w, float4 s0, float4 s1, float& acc)
{
    float2 f;
    f = __half22float2(*reinterpret_cast<const __half2*>(&w.x));
    acc = fmaf(f.x, s0.x, acc); acc = fmaf(f.y, s0.y, acc);
    f = __half22float2(*reinterpret_cast<const __half2*>(&w.y));
    acc = fmaf(f.x, s0.z, acc); acc = fmaf(f.y, s0.w, acc);
    f = __half22float2(*reinterpret_cast<const __half2*>(&w.z));
    acc = fmaf(f.x, s1.x, acc); acc = fmaf(f.y, s1.y, acc);
    f = __half22float2(*reinterpret_cast<const __half2*>(&w.w));
    acc = fmaf(f.x, s1.z, acc); acc = fmaf(f.y, s1.w, acc);
}

// ---------------------------------------------------------------------------
// Software grid barrier (persistent kernel, all CTAs co-resident).
// ---------------------------------------------------------------------------
__device__ __forceinline__ void grid_barrier(int nctas)
{
    __syncthreads();
    if (threadIdx.x == 0) {
        __threadfence();                      // release
        unsigned gen = g_gen;
        if (atomicAdd(&g_count, 1u) == (unsigned)(nctas - 1)) {
            g_count = 0;
            __threadfence();
            g_gen = gen + 1u;
        } else {
            while (g_gen == gen) { }
        }
        __threadfence();                      // acquire
    }
    __syncthreads();
}

// ---------------------------------------------------------------------------
// Convert Wres fp32 -> fp16 (once per launch; ~100 MB traffic, ~30us)
// ---------------------------------------------------------------------------
__global__ __launch_bounds__(256) void convert_wres_kernel(const float* __restrict__ W)
{
    const size_t n8 = (size_t)RR * RR / 8;
    uint4* out = reinterpret_cast<uint4*>(g_wres_h);
    const float4* in = reinterpret_cast<const float4*>(W);
    for (size_t k = (size_t)blockIdx.x * blockDim.x + threadIdx.x;
         k < n8; k += (size_t)gridDim.x * blockDim.x) {
        float4 a = ldcg4f(in + 2 * k);
        float4 b = ldcg4f(in + 2 * k + 1);
        uint4 o;
        __half2 h;
        h = __floats2half2_rn(a.x, a.y); o.x = *reinterpret_cast<uint32_t*>(&h);
        h = __floats2half2_rn(a.z, a.w); o.y = *reinterpret_cast<uint32_t*>(&h);
        h = __floats2half2_rn(b.x, b.y); o.z = *reinterpret_cast<uint32_t*>(&h);
        h = __floats2half2_rn(b.z, b.w); o.w = *reinterpret_cast<uint32_t*>(&h);
        out[k] = o;
    }
}

// ---------------------------------------------------------------------------
// GEMM 1: g_u[t][r] = sum_d x[t,d] * Win_w[r,d] + Win_b[r]
// ---------------------------------------------------------------------------
__global__ __launch_bounds__(256) void gemm_u_kernel(
    const float* __restrict__ A, const float* __restrict__ B,
    const float* __restrict__ bias)
{
    const int K = DIN;
    __shared__ float As[8][128];
    __shared__ float Bs[8][128];

    const int bm = blockIdx.y * 128;
    const int bn = blockIdx.x * 128;
    const int tid = threadIdx.x;
    const int tm = (tid >> 4) * 8;
    const int tn = (tid & 15) * 8;
    const int lr = tid >> 1;
    const int lc = (tid & 1) * 4;

    float acc[8][8];
    #pragma unroll
    for (int i = 0; i < 8; i++)
        #pragma unroll
        for (int j = 0; j < 8; j++) acc[i][j] = 0.f;

    for (int kb = 0; kb < K; kb += 8) {
        float4 a = *reinterpret_cast<const float4*>(&A[(size_t)(bm + lr) * K + kb + lc]);
        float4 b = *reinterpret_cast<const float4*>(&B[(size_t)(bn + lr) * K + kb + lc]);
        __syncthreads();
        As[lc + 0][lr] = a.x; As[lc + 1][lr] = a.y; As[lc + 2][lr] = a.z; As[lc + 3][lr] = a.w;
        Bs[lc + 0][lr] = b.x; Bs[lc + 1][lr] = b.y; Bs[lc + 2][lr] = b.z; Bs[lc + 3][lr] = b.w;
        __syncthreads();
        #pragma unroll
        for (int k = 0; k < 8; k++) {
            float4 a0 = *reinterpret_cast<const float4*>(&As[k][tm]);
            float4 a1 = *reinterpret_cast<const float4*>(&As[k][tm + 4]);
            float4 b0 = *reinterpret_cast<const float4*>(&Bs[k][tn]);
            float4 b1 = *reinterpret_cast<const float4*>(&Bs[k][tn + 4]);
            float ar[8] = {a0.x, a0.y, a0.z, a0.w, a1.x, a1.y, a1.z, a1.w};
            float br[8] = {b0.x, b0.y, b0.z, b0.w, b1.x, b1.y, b1.z, b1.w};
            #pragma unroll
            for (int i = 0; i < 8; i++)
                #pragma unroll
                for (int j = 0; j < 8; j++)
                    acc[i][j] = fmaf(ar[i], br[j], acc[i][j]);
        }
    }

    #pragma unroll
    for (int i = 0; i < 8; i++)
        #pragma unroll
        for (int j = 0; j < 8; j++)
            g_u[(size_t)(bm + tm + i) * RR + (bn + tn + j)] = acc[i][j] + bias[bn + tn + j];
}

// ---------------------------------------------------------------------------
// Persistent recurrence, fp16 weights, SMEM-resident split.
// Each CTA owns <=28 rows; cols [0,C_SH) of those rows live in SMEM (half),
// cols [C_SH,RR) stream from L2 (half). s fp32 staged in SMEM per step.
// 2 rows per warp (shares s reads).
// ---------------------------------------------------------------------------
extern __shared__ unsigned char s_dyn[];

__global__ __launch_bounds__(1024, 1) void recur_smem_kernel(int nctas)
{
    __half* wsh  = reinterpret_cast<__half*>(s_dyn);             // ROWS_MAX*C_SH
    float*  s_sh = reinterpret_cast<float*>(s_dyn + (size_t)ROWS_MAX * C_SH * 2);
    float4* s_sh4 = reinterpret_cast<float4*>(s_sh);

    const int cta   = blockIdx.x;
    const int r0    = (cta * RR) / nctas;
    const int r1    = ((cta + 1) * RR) / nctas;
    const int nrows = r1 - r0;
    const int warp  = threadIdx.x >> 5;
    const int lane  = threadIdx.x & 31;
    const int tid   = threadIdx.x;

    // Prologue: copy resident weight block (half) into SMEM
    {
        const int tot = nrows * (C_SH8);   // uint4 chunks
        uint4* wsh4 = reinterpret_cast<uint4*>(wsh);
        for (int idx = tid; idx < tot; idx += 1024) {
            int lrow = idx / C_SH8;
            int c8   = idx - lrow * C_SH8;
            wsh4[(size_t)lrow * C_SH8 + c8] =
                ldcg4u(reinterpret_cast<const uint4*>(g_wres_h + (size_t)(r0 + lrow) * RR) + c8);
        }
    }

    // step 0
    if (tid < nrows) {
        int r = r0 + tid;
        g_states[r] = tanhf(ldcg(&g_u[r]));
    }
    grid_barrier(nctas);

    const int npairs = (nrows + 1) >> 1;
    const int rowA = r0 + 2 * warp;
    const int rowB = rowA + 1;
    const bool active = (warp < npairs);
    const bool haveB  = active && (rowB < r1);

    const uint4* wgA = reinterpret_cast<const uint4*>(g_wres_h + (size_t)rowA * RR + C_SH);
    const uint4* wgB = reinterpret_cast<const uint4*>(g_wres_h + (size_t)rowB * RR + C_SH);
    const uint4* wsA = reinterpret_cast<const uint4*>(wsh + (size_t)(2 * warp) * C_SH);
    const uint4* wsB = reinterpret_cast<const uint4*>(wsh + (size_t)(2 * warp + 1) * C_SH);

    for (int t = 1; t < T_; ++t) {
        // Stage s_{t-1}
        {
            const float4* sp4 = reinterpret_cast<const float4*>(
                g_states + (size_t)(t - 1) * RR);
            s_sh4[tid] = ldcg4f(sp4 + tid);
        }
        __syncthreads();

        if (active) {
            float accA = 0.f, accB = 0.f;

            // L2-streamed tail first (get loads in flight early)
            uint4 ta[2], tb[2];
            #pragma unroll
            for (int k = 0; k < 2; k++) {
                int idx = lane + 32 * k;   // < REM8 (=64)
                ta[k] = ldcg4u(wgA + idx);
                if (haveB) tb[k] = ldcg4u(wgB + idx);
            }

            // SMEM-resident columns
            #pragma unroll 2
            for (int idx = lane; idx < C_SH8; idx += 32) {
                float4 s0 = s_sh4[2 * idx];
                float4 s1 = s_sh4[2 * idx + 1];
                fma8(wsA[idx], s0, s1, accA);
                if (haveB) fma8(wsB[idx], s0, s1, accB);
            }
            // streamed tail FMAs
            #pragma unroll
            for (int k = 0; k < 2; k++) {
                int idx = lane + 32 * k;
                float4 s0 = s_sh4[2 * (C_SH / 8 + idx)];
                float4 s1 = s_sh4[2 * (C_SH / 8 + idx) + 1];
                fma8(ta[k], s0, s1, accA);
                if (haveB) fma8(tb[k], s0, s1, accB);
            }

            #pragma unroll
            for (int o = 16; o; o >>= 1) {
                accA += __shfl_xor_sync(0xffffffffu, accA, o);
                accB += __shfl_xor_sync(0xffffffffu, accB, o);
            }
            if (lane == 0) {
                const float* u_t = g_u + (size_t)t * RR;
                float* scur = g_states + (size_t)t * RR;
                float xiA = tanhf(ldcg(&u_t[rowA]) + accA);
                scur[rowA] = (1.0f - LEAK_) * s_sh[rowA] + LEAK_ * xiA;
                if (haveB) {
                    float xiB = tanhf(ldcg(&u_t[rowB]) + accB);
                    scur[rowB] = (1.0f - LEAK_) * s_sh[rowB] + LEAK_ * xiB;
                }
            }
        }
        grid_barrier(nctas);
    }
}

// ---------------------------------------------------------------------------
// Fallback recurrence: fp16 weights streamed fully from L2, one warp/row,
// s staged in static SMEM. No dynamic SMEM -> always resident.
// ---------------------------------------------------------------------------
__global__ __launch_bounds__(1024, 1) void recur_fallback(int nctas)
{
    __shared__ float fs[RR];
    float4* fs4 = reinterpret_cast<float4*>(fs);

    const int cta   = blockIdx.x;
    const int r0    = (cta * RR) / nctas;
    const int r1    = ((cta + 1) * RR) / nctas;
    const int nrows = r1 - r0;
    const int warp  = threadIdx.x >> 5;
    const int lane  = threadIdx.x & 31;
    const int tid   = threadIdx.x;

    if (tid < nrows) {
        int r = r0 + tid;
        g_states[r] = tanhf(ldcg(&g_u[r]));
    }
    grid_barrier(nctas);

    const int r = r0 + warp;
    const bool active = (warp < nrows);
    const uint4* wrow = reinterpret_cast<const uint4*>(g_wres_h + (size_t)r * RR);

    for (int t = 1; t < T_; ++t) {
        {
            const float4* sp4 = reinterpret_cast<const float4*>(
                g_states + (size_t)(t - 1) * RR);
            fs4[tid] = ldcg4f(sp4 + tid);
        }
        __syncthreads();

        if (active) {
            float acc = 0.f;
            #pragma unroll 4
            for (int idx = lane; idx < RR / 8; idx += 32) {
                uint4 w = ldcg4u(wrow + idx);
                float4 s0 = fs4[2 * idx];
                float4 s1 = fs4[2 * idx + 1];
                fma8(w, s0, s1, acc);
            }
            #pragma unroll
            for (int o = 16; o; o >>= 1)
                acc += __shfl_xor_sync(0xffffffffu, acc, o);
            if (lane == 0) {
                float xi = tanhf(ldcg(&g_u[(size_t)t * RR + r]) + acc);
                g_states[(size_t)t * RR + r] = (1.0f - LEAK_) * fs[r] + LEAK_ * xi;
            }
        }
        grid_barrier(nctas);
    }
}

// ---------------------------------------------------------------------------
// GEMM 2: yout = concat(x, states) @ Wout^T + b
// ---------------------------------------------------------------------------
__global__ __launch_bounds__(256) void gemm_out_kernel(
    const float* __restrict__ x, const float* __restrict__ Wout,
    const float* __restrict__ bias, float* __restrict__ C)
{
    const int K = NINT;
    __shared__ float As[8][128];
    __shared__ float Bs[8][128];

    const int bm = blockIdx.y * 128;
    const int bn = blockIdx.x * 128;
    const int tid = threadIdx.x;
    const int tm = (tid >> 4) * 8;
    const int tn = (tid & 15) * 8;
    const int lr = tid >> 1;
    const int lc = (tid & 1) * 4;

    float acc[8][8];
    #pragma unroll
    for (int i = 0; i < 8; i++)
        #pragma unroll
        for (int j = 0; j < 8; j++) acc[i][j] = 0.f;

    for (int kb = 0; kb < K; kb += 8) {
        const int row = bm + lr;
        const int kk  = kb + lc;
        float4 a;
        if (kk < DIN)
            a = *reinterpret_cast<const float4*>(&x[(size_t)row * DIN + kk]);
        else
            a = *reinterpret_cast<const float4*>(&g_states[(size_t)row * RR + (kk - DIN)]);
        float4 b = *reinterpret_cast<const float4*>(&Wout[(size_t)(bn + lr) * K + kk]);
        __syncthreads();
        As[lc + 0][lr] = a.x; As[lc + 1][lr] = a.y; As[lc + 2][lr] = a.z; As[lc + 3][lr] = a.w;
        Bs[lc + 0][lr] = b.x; Bs[lc + 1][lr] = b.y; Bs[lc + 2][lr] = b.z; Bs[lc + 3][lr] = b.w;
        __syncthreads();
        #pragma unroll
        for (int k = 0; k < 8; k++) {
            float4 a0 = *reinterpret_cast<const float4*>(&As[k][tm]);
            float4 a1 = *reinterpret_cast<const float4*>(&As[k][tm + 4]);
            float4 b0 = *reinterpret_cast<const float4*>(&Bs[k][tn]);
            float4 b1 = *reinterpret_cast<const float4*>(&Bs[k][tn + 4]);
            float ar[8] = {a0.x, a0.y, a0.z, a0.w, a1.x, a1.y, a1.z, a1.w};
            float br[8] = {b0.x, b0.y, b0.z, b0.w, b1.x, b1.y, b1.z, b1.w};
            #pragma unroll
            for (int i = 0; i < 8; i++)
                #pragma unroll
                for (int j = 0; j < 8; j++)
                    acc[i][j] = fmaf(ar[i], br[j], acc[i][j]);
        }
    }

    #pragma unroll
    for (int i = 0; i < 8; i++)
        #pragma unroll
        for (int j = 0; j < 8; j++)
            C[(size_t)(bm + tm + i) * DOUT + (bn + tn + j)] = acc[i][j] + bias[bn + tn + j];
}

// ---------------------------------------------------------------------------
extern "C" void kernel_launch(void* const* d_in, const int* in_sizes, int n_in,
                              void* d_out, int out_size)
{
    const float* x      = (const float*)d_in[0];
    const float* Win_w  = (const float*)d_in[1];
    const float* Win_b  = (const float*)d_in[2];
    const float* Wres_w = (const float*)d_in[3];
    const float* Wout_w = (const float*)d_in[4];
    const float* Wout_b = (const float*)d_in[5];
    float* yout = (float*)d_out;

    int dev = 0;
    cudaGetDevice(&dev);
    int sms = NCTAS;
    cudaDeviceGetAttribute(&sms, cudaDevAttrMultiProcessorCount, dev);
    if (sms < 1 || sms > NCTAS) sms = NCTAS;

    cudaError_t attr_err = cudaFuncSetAttribute(
        recur_smem_kernel, cudaFuncAttributeMaxDynamicSharedMemorySize, (int)SMEM_BYTES);
    int nblk = 0;
    cudaError_t occ_err = cudaOccupancyMaxActiveBlocksPerMultiprocessor(
        &nblk, recur_smem_kernel, 1024, SMEM_BYTES);
    const bool use_smem = (attr_err == cudaSuccess) &&
                          (occ_err == cudaSuccess) && (nblk >= 1);

    convert_wres_kernel<<<1024, 256>>>(Wres_w);

    dim3 g1(RR / 128, T_ / 128);
    gemm_u_kernel<<<g1, 256>>>(x, Win_w, Win_b);

    if (use_smem)
        recur_smem_kernel<<<sms, 1024, SMEM_BYTES>>>(sms);
    else
        recur_fallback<<<sms, 1024>>>(sms);

    dim3 g2(DOUT / 128, T_ / 128);
    gemm_out_kernel<<<g2, 256>>>(x, Wout_w, Wout_b, yout);

    (void)in_sizes; (void)n_in; (void)out_size;
}